// round 11
// baseline (speedup 1.0000x reference)
#include <cuda_runtime.h>
#include <cstdint>

#define N_ 64
#define C_ 64
#define T_ 300
#define V_ 25
#define S_ 3
#define IC_ 16
#define OC_ 64
#define EPS_ 1e-5f
#define TV_ (T_ * V_)

#define NCH 75
#define PP 100

#define P68 68     // 272B pitch (272/16=17 odd -> ldmatrix conflict-free)
#define P36 36     // 144B pitch (144/16=9 odd)

// ---- device-global scratch ----
__device__ float g_Mpart[N_ * NCH * S_ * 625];
__device__ float g_AadpT[N_ * S_ * 25 * P36];   // [n][s][w][v] tf32, v-pads zero
__device__ float g_wabM[96 * P68];              // [r=s*32+j][c] tf32
__device__ float g_wdO[S_ * OC_ * P68];         // [s][o][c] tf32
__device__ float g_bnc[192];                    // mul[96], add[96]
__device__ float g_obnc[128];                   // sc[64], sh[64]

__device__ __forceinline__ float tanh_fast(float x) {
    float cx = fminf(fmaxf(x, -10.0f), 10.0f);
    float e = __expf(2.0f * cx);
    return __fdividef(e - 1.0f, e + 1.0f);
}
__device__ __forceinline__ float to_tf32(float x) {
    uint32_t u;
    asm("cvt.rna.tf32.f32 %0, %1;" : "=r"(u) : "f"(x));
    return __uint_as_float(u);
}
__device__ __forceinline__ void mma_tf32(float c[4],
                                         uint32_t a0, uint32_t a1, uint32_t a2, uint32_t a3,
                                         uint32_t b0, uint32_t b1) {
    asm volatile("mma.sync.aligned.m16n8k8.row.col.f32.tf32.tf32.f32 "
                 "{%0,%1,%2,%3}, {%4,%5,%6,%7}, {%8,%9}, {%0,%1,%2,%3};"
                 : "+f"(c[0]), "+f"(c[1]), "+f"(c[2]), "+f"(c[3])
                 : "r"(a0), "r"(a1), "r"(a2), "r"(a3), "r"(b0), "r"(b1));
}
__device__ __forceinline__ void ldsm_x4(uint32_t& r0, uint32_t& r1, uint32_t& r2, uint32_t& r3,
                                        uint32_t a) {
    asm volatile("ldmatrix.sync.aligned.m8n8.x4.shared.b16 {%0,%1,%2,%3}, [%4];"
                 : "=r"(r0), "=r"(r1), "=r"(r2), "=r"(r3) : "r"(a));
}
__device__ __forceinline__ void ldsm_x2(uint32_t& r0, uint32_t& r1, uint32_t a) {
    asm volatile("ldmatrix.sync.aligned.m8n8.x2.shared.b16 {%0,%1}, [%2];"
                 : "=r"(r0), "=r"(r1) : "r"(a));
}
__device__ __forceinline__ uint32_t smem_u32(const void* p) {
    return (uint32_t)__cvta_generic_to_shared(p);
}

// =====================================================================
// k0: one-time prep of weight layouts + BN constants
// =====================================================================
__global__ void k0_prep(const float* __restrict__ wa, const float* __restrict__ ba,
                        const float* __restrict__ wb, const float* __restrict__ bb,
                        const float* __restrict__ gaA, const float* __restrict__ beA,
                        const float* __restrict__ mA,  const float* __restrict__ vA,
                        const float* __restrict__ gaB, const float* __restrict__ beB,
                        const float* __restrict__ mB,  const float* __restrict__ vB,
                        const float* __restrict__ wd,  const float* __restrict__ dbias,
                        const float* __restrict__ bng, const float* __restrict__ bnb,
                        const float* __restrict__ bnm, const float* __restrict__ bnv)
{
    int gid = blockIdx.x * blockDim.x + threadIdx.x;
    if (gid < 96 * P68) {
        int r = gid / P68, c = gid % P68;
        float val = 0.0f;
        if (c < C_) {
            int s = r >> 5, j = r & 31;
            val = (j < IC_) ? wa[(s * IC_ + j) * C_ + c]
                            : wb[(s * IC_ + (j - 16)) * C_ + c];
            val = to_tf32(val);
        }
        g_wabM[gid] = val;
        return;
    }
    int g2 = gid - 96 * P68;
    if (g2 < S_ * OC_ * P68) {
        int so = g2 / P68, c = g2 % P68;
        g_wdO[g2] = (c < C_) ? to_tf32(wd[so * C_ + c]) : 0.0f;
        return;
    }
    int g3 = g2 - S_ * OC_ * P68;
    if (g3 < 96) {
        int s = g3 >> 5, j = g3 & 31;
        int i = (j < IC_) ? j : j - 16;
        int off = s * IC_ + i;
        float g, be, mm, vv, bias;
        if (j < IC_) { g = gaA[off]; be = beA[off]; mm = mA[off]; vv = vA[off]; bias = ba[off]; }
        else         { g = gaB[off]; be = beB[off]; mm = mB[off]; vv = vB[off]; bias = bb[off]; }
        float sc = g * rsqrtf(vv + EPS_);
        g_bnc[g3] = sc;
        g_bnc[96 + g3] = be + (bias - mm) * sc;
        return;
    }
    int g4 = g3 - 96;
    if (g4 < OC_) {
        float scv = bng[g4] * rsqrtf(bnv[g4] + EPS_);
        g_obnc[g4] = scv;
        g_obnc[64 + g4] = bnb[g4] + (dbias[g4] + dbias[OC_ + g4] + dbias[2 * OC_ + g4] - bnm[g4]) * scv;
    }
}

// =====================================================================
// k1: per (n, 4-t chunk):
//  stage1: [96 x 100 x 64] MMA via ldmatrix, BN+tanh on frags,
//          scatter into astM/bstM [v][k=(i,tl)]
//  stage2: per s, M[25x25] = a^T b via ldmatrix -> gmem partials
// smem 13616 floats = 54464B -> 3 CTAs/SM
// =====================================================================
__global__ __launch_bounds__(256, 3)
void k1_mpart(const float* __restrict__ x)
{
    extern __shared__ float sm1[];
    float* wabM = sm1;           // 96*68 = 6528   [r][c]
    float* xs2  = sm1 + 6528;    // 100*68 = 6800  [p][c] (+overrun pad)
    float* ab2  = sm1;           // stage2 overlay: [s][ast 25*68][bst 25*68] = 10200

    const int n = blockIdx.y, chunk = blockIdx.x, tid = threadIdx.x;
    const int lane = tid & 31, warp = tid >> 5;
    const int qk = lane & 3, qm = lane >> 2;

    // ---- stage wabM: linear f4 copy
    for (int idx = tid; idx < 6528 / 4; idx += 256)
        ((float4*)wabM)[idx] = ((const float4*)g_wabM)[idx];
    // ---- stage xs2 [p][c] via 4x4 register-tile transpose (coalesced LDG)
    const float* xbase = x + (size_t)n * (C_ * TV_) + chunk * PP;
    for (int t = tid; t < 400; t += 256) {
        int q = t % 25, c4 = t / 25;
        const float* src = xbase + (c4 * 4) * TV_ + q * 4;
        float4 r0 = *(const float4*)(src);
        float4 r1 = *(const float4*)(src + TV_);
        float4 r2 = *(const float4*)(src + 2 * TV_);
        float4 r3 = *(const float4*)(src + 3 * TV_);
        float4 o;
        o.x = r0.x; o.y = r1.x; o.z = r2.x; o.w = r3.x;
        *(float4*)(xs2 + (4 * q + 0) * P68 + c4 * 4) = o;
        o.x = r0.y; o.y = r1.y; o.z = r2.y; o.w = r3.y;
        *(float4*)(xs2 + (4 * q + 1) * P68 + c4 * 4) = o;
        o.x = r0.z; o.y = r1.z; o.z = r2.z; o.w = r3.z;
        *(float4*)(xs2 + (4 * q + 2) * P68 + c4 * 4) = o;
        o.x = r0.w; o.y = r1.w; o.z = r2.w; o.w = r3.w;
        *(float4*)(xs2 + (4 * q + 3) * P68 + c4 * 4) = o;
    }
    __syncthreads();

    // ---- stage1: warps 0..5 own m-strip mt=warp; 13 nt; K=64
    float acc[13][4];
    if (warp < 6) {
        #pragma unroll
        for (int t = 0; t < 13; ++t)
            #pragma unroll
            for (int r = 0; r < 4; ++r) acc[t][r] = 0.0f;
        const uint32_t abase = smem_u32(wabM) + (warp * 16 + (lane & 15)) * 272
                             + ((lane >> 4) << 4);
        const uint32_t bbase = smem_u32(xs2) + (lane & 7) * 272 + (((lane >> 3) & 1) << 4);
        #pragma unroll
        for (int k0 = 0; k0 < 8; ++k0) {
            uint32_t a0, a1, a2, a3;
            ldsm_x4(a0, a1, a2, a3, abase + k0 * 32);
            #pragma unroll
            for (int nt = 0; nt < 13; ++nt) {
                uint32_t b0, b1;
                ldsm_x2(b0, b1, bbase + nt * 8 * 272 + k0 * 32);
                mma_tf32(acc[nt], a0, a1, a2, a3, b0, b1);
            }
        }
    }
    __syncthreads();   // done with wabM/xs2; overlay writable

    // ---- BN + tanh, scatter to astM/bstM [v][i*4+tl]
    if (warp < 6) {
        #pragma unroll
        for (int half = 0; half < 2; ++half) {
            int r = warp * 16 + qm + half * 8;
            float mu = g_bnc[r], ad = g_bnc[96 + r];
            int s = r >> 5, j = r & 31, i = j & 15;
            float* dstb = ab2 + s * 3400 + ((j < IC_) ? 0 : 1700);
            #pragma unroll
            for (int nt = 0; nt < 13; ++nt) {
                #pragma unroll
                for (int e = 0; e < 2; ++e) {
                    int p = nt * 8 + qk * 2 + e;
                    if (p < PP) {
                        int tl = p / 25, v = p - tl * 25;
                        float val = tanh_fast(fmaf(acc[nt][half * 2 + e], mu, ad));
                        dstb[v * P68 + i * 4 + tl] = val;
                    }
                }
            }
        }
    }
    __syncthreads();

    // ---- stage2: 24 tasks (s, mtv, ntw), 3/warp, K=64, ldmatrix both sides
    float* dst = g_Mpart + (size_t)(n * NCH + chunk) * (S_ * 625);
    #pragma unroll
    for (int ti = 0; ti < 3; ++ti) {
        int task = warp * 3 + ti;
        int s = task >> 3, mtv = (task >> 2) & 1, ntw = task & 3;
        const uint32_t abase = smem_u32(ab2 + s * 3400)
                             + (mtv * 16 + (lane & 15)) * 272 + ((lane >> 4) << 4);
        const uint32_t bbase = smem_u32(ab2 + s * 3400 + 1700)
                             + (ntw * 8 + (lane & 7)) * 272 + (((lane >> 3) & 1) << 4);
        float acc2[4] = {0.0f, 0.0f, 0.0f, 0.0f};
        #pragma unroll
        for (int k0 = 0; k0 < 8; ++k0) {
            uint32_t a0, a1, a2, a3, b0, b1;
            ldsm_x4(a0, a1, a2, a3, abase + k0 * 32);
            ldsm_x2(b0, b1, bbase + k0 * 32);
            mma_tf32(acc2, a0, a1, a2, a3, b0, b1);
        }
        #pragma unroll
        for (int half = 0; half < 2; ++half) {
            int v = mtv * 16 + qm + half * 8;
            #pragma unroll
            for (int e = 0; e < 2; ++e) {
                int w = ntw * 8 + qk * 2 + e;
                if (v < V_ && w < V_)
                    dst[s * 625 + v * 25 + w] = acc2[half * 2 + e];
            }
        }
    }
}

// =====================================================================
// k2: reduce partial M -> g_AadpT [n][s][w][v] tf32 (transposed, padded)
// =====================================================================
__global__ void k2_aadp(const float* __restrict__ A, const float* __restrict__ alpha)
{
    int gid = blockIdx.x * blockDim.x + threadIdx.x;
    if (gid >= N_ * S_ * 25 * P36) return;
    int n = gid / (S_ * 25 * P36);
    int rem = gid % (S_ * 25 * P36);
    int s = rem / (25 * P36);
    int r = rem % (25 * P36);
    int w = r / P36, v = r % P36;
    float val = 0.0f;
    if (v < V_) {
        const float* src = g_Mpart + (size_t)n * NCH * (S_ * 625) + s * 625 + v * 25 + w;
        float sum = 0.0f;
        #pragma unroll 5
        for (int ch = 0; ch < NCH; ++ch) sum += src[(size_t)ch * (S_ * 625)];
        val = to_tf32(A[s * 625 + v * 25 + w] + tanh_fast(sum * (1.0f / 4800.0f)) * alpha[0]);
    }
    g_AadpT[gid] = val;
}

// =====================================================================
// k3: per (n, 4-t chunk):
//  phase1: U[(c,tl)][w] = xsA[m][k=v] x as3T (m=256,n=32,k=32) -> us2 [p][c]
//  phase2: Y[o][p] += wdO (gmem A) x us2 (m=64,n=104,k=64)
//  epilogue: BN + residual + relu
// smem 18716 floats = 74864B -> 3 CTAs/SM
// =====================================================================
__global__ __launch_bounds__(256, 3)
void k3_main(const float* __restrict__ x, float* __restrict__ out)
{
    extern __shared__ float sm3[];
    float* as3T = sm3;           // 3*25*36 = 2700 [s][w][v] (+overrun into us2)
    float* us2  = sm3 + 2700;    // 100*68 = 6800 [p][c] (+overrun into xsA)
    float* xsA  = sm3 + 9500;    // 256*36 = 9216 [(c,tl)][v]

    const int n = blockIdx.y, chunk = blockIdx.x, tid = threadIdx.x;
    const int lane = tid & 31, warp = tid >> 5;
    const int qk = lane & 3, qm = lane >> 2;

    const float* xbase = x + (size_t)n * (C_ * TV_) + chunk * PP;

    // ---- stage xsA: coalesced f4 LDG, scalar STS into [m=(c,tl)][v]
    for (int idx4 = tid; idx4 < 64 * 25; idx4 += 256) {
        int c = idx4 / 25, q = idx4 % 25;
        float4 r = *(const float4*)(xbase + c * TV_ + q * 4);
        #pragma unroll
        for (int j = 0; j < 4; ++j) {
            int p = 4 * q + j;
            int tl = p / 25, v = p - tl * 25;
            float val = (j == 0) ? r.x : (j == 1) ? r.y : (j == 2) ? r.z : r.w;
            xsA[(c * 4 + tl) * P36 + v] = val;
        }
    }
    // zero xsA k-pad cols 25..31 (they multiply as3T's zero rows; avoid NaN*0)
    for (int idx = tid; idx < 256 * 7; idx += 256) {
        int row = idx / 7, cc = 25 + idx % 7;
        xsA[row * P36 + cc] = 0.0f;
    }
    // ---- stage as3T: linear f4 copy
    {
        const float4* src = (const float4*)(g_AadpT + (size_t)n * (S_ * 25 * P36));
        for (int idx = tid; idx < (S_ * 25 * P36) / 4; idx += 256)
            ((float4*)as3T)[idx] = src[idx];
    }
    __syncthreads();

    const int mtY = warp >> 1;
    const int ntb = (warp & 1) ? 7 : 0;
    const int nnt = (warp & 1) ? 6 : 7;
    float accY[7][4];
    #pragma unroll
    for (int t = 0; t < 7; ++t)
        #pragma unroll
        for (int r = 0; r < 4; ++r) accY[t][r] = 0.0f;

    const uint32_t aoff = (lane & 15) * 144 + ((lane >> 4) << 4);
    const uint32_t boff36 = (lane & 7) * 144 + (((lane >> 3) & 1) << 4);
    const uint32_t boff68 = (lane & 7) * 272 + (((lane >> 3) & 1) << 4);

    for (int s = 0; s < S_; ++s) {
        // ---- phase1: warp owns m-tiles {warp, warp+8}; 4 nt; K=32
        {
            float acc1[2][4][4];
            #pragma unroll
            for (int m2 = 0; m2 < 2; ++m2)
                #pragma unroll
                for (int t = 0; t < 4; ++t)
                    #pragma unroll
                    for (int r = 0; r < 4; ++r) acc1[m2][t][r] = 0.0f;
            const uint32_t ab0 = smem_u32(xsA) + warp * 16 * 144 + aoff;
            const uint32_t ab1 = ab0 + 8 * 16 * 144;
            const uint32_t bb = smem_u32(as3T) + s * 900 * 4 + boff36;
            #pragma unroll
            for (int k0 = 0; k0 < 4; ++k0) {
                uint32_t a[2][4];
                ldsm_x4(a[0][0], a[0][1], a[0][2], a[0][3], ab0 + k0 * 32);
                ldsm_x4(a[1][0], a[1][1], a[1][2], a[1][3], ab1 + k0 * 32);
                #pragma unroll
                for (int nt = 0; nt < 4; ++nt) {
                    uint32_t b0, b1;
                    ldsm_x2(b0, b1, bb + nt * 8 * 144 + k0 * 32);
                    mma_tf32(acc1[0][nt], a[0][0], a[0][1], a[0][2], a[0][3], b0, b1);
                    mma_tf32(acc1[1][nt], a[1][0], a[1][1], a[1][2], a[1][3], b0, b1);
                }
            }
            // scatter U -> us2[p][c]
            #pragma unroll
            for (int m2 = 0; m2 < 2; ++m2) {
                #pragma unroll
                for (int half = 0; half < 2; ++half) {
                    int m = (warp + m2 * 8) * 16 + qm + half * 8;
                    int c = m >> 2, tl = m & 3;
                    #pragma unroll
                    for (int nt = 0; nt < 4; ++nt) {
                        #pragma unroll
                        for (int e = 0; e < 2; ++e) {
                            int w = nt * 8 + qk * 2 + e;
                            if (w < V_)
                                us2[(tl * 25 + w) * P68 + c] = acc1[m2][nt][half * 2 + e];
                        }
                    }
                }
            }
        }
        __syncthreads();

        // ---- phase2: A scalar LDG from g_wdO (L1-hot), B x2-ldmatrix from us2
        const float* wdb = g_wdO + s * (OC_ * P68) + (mtY * 16 + qm) * P68 + qk;
        const uint32_t ub = smem_u32(us2) + boff68;
        #pragma unroll
        for (int k0 = 0; k0 < 8; ++k0) {
            int kk = k0 * 8;
            uint32_t a0 = __float_as_uint(wdb[kk]);
            uint32_t a1 = __float_as_uint(wdb[8 * P68 + kk]);
            uint32_t a2 = __float_as_uint(wdb[kk + 4]);
            uint32_t a3 = __float_as_uint(wdb[8 * P68 + kk + 4]);
            #pragma unroll
            for (int j = 0; j < 7; ++j) {
                if (j < nnt) {
                    int nt = ntb + j;
                    uint32_t b0, b1;
                    ldsm_x2(b0, b1, ub + nt * 8 * 272 + k0 * 32);
                    mma_tf32(accY[j], a0, a1, a2, a3, b0, b1);
                }
            }
        }
        __syncthreads();   // us2 consumed; next s may overwrite
    }

    // ---- epilogue: BN + residual + relu
    float* obase = out + (size_t)n * (C_ * TV_) + chunk * PP;
    #pragma unroll
    for (int half = 0; half < 2; ++half) {
        int o = mtY * 16 + qm + half * 8;
        float sc = g_obnc[o], sh = g_obnc[64 + o];
        const float* xr = xbase + o * TV_;
        float* orow = obase + o * TV_;
        #pragma unroll
        for (int j = 0; j < 7; ++j) {
            if (j < nnt) {
                int nt = ntb + j;
                #pragma unroll
                for (int e = 0; e < 2; ++e) {
                    int p = nt * 8 + qk * 2 + e;
                    if (p < PP) {
                        float val = fmaf(accY[j][half * 2 + e], sc, sh) + xr[p];
                        orow[p] = fmaxf(val, 0.0f);
                    }
                }
            }
        }
    }
}

// =====================================================================
extern "C" void kernel_launch(void* const* d_in, const int* in_sizes, int n_in,
                              void* d_out, int out_size)
{
    const float* x    = (const float*)d_in[0];
    const float* A    = (const float*)d_in[1];
    const float* alph = (const float*)d_in[2];
    const float* wa   = (const float*)d_in[3];
    const float* ba   = (const float*)d_in[4];
    const float* wb   = (const float*)d_in[5];
    const float* bb   = (const float*)d_in[6];
    const float* bag  = (const float*)d_in[7];
    const float* bab  = (const float*)d_in[8];
    const float* bam  = (const float*)d_in[9];
    const float* bav  = (const float*)d_in[10];
    const float* bbg  = (const float*)d_in[11];
    const float* bbb  = (const float*)d_in[12];
    const float* bbm  = (const float*)d_in[13];
    const float* bbv  = (const float*)d_in[14];
    const float* wd   = (const float*)d_in[15];
    const float* db   = (const float*)d_in[16];
    const float* bng  = (const float*)d_in[17];
    const float* bnbt = (const float*)d_in[18];
    const float* bnm  = (const float*)d_in[19];
    const float* bnv  = (const float*)d_in[20];
    float* out = (float*)d_out;

    const int SM1 = 13616 * (int)sizeof(float); // 54464 B -> 3 CTAs
    const int SM3 = 18716 * (int)sizeof(float); // 74864 B -> 3 CTAs
    cudaFuncSetAttribute(k1_mpart, cudaFuncAttributeMaxDynamicSharedMemorySize, SM1);
    cudaFuncSetAttribute(k3_main,  cudaFuncAttributeMaxDynamicSharedMemorySize, SM3);

    int prep_elems = 96 * P68 + S_ * OC_ * P68 + 96 + OC_;
    k0_prep<<<(prep_elems + 255) / 256, 256>>>(
        wa, ba, wb, bb, bag, bab, bam, bav, bbg, bbb, bbm, bbv,
        wd, db, bng, bnbt, bnm, bnv);

    dim3 g(NCH, N_);
    k1_mpart<<<g, 256, SM1>>>(x);

    k2_aadp<<<(N_ * S_ * 25 * P36 + 255) / 256, 256>>>(A, alph);

    k3_main<<<g, 256, SM3>>>(x, out);
}

// round 15
// speedup vs baseline: 1.0750x; 1.0750x over previous
#include <cuda_runtime.h>
#include <cstdint>

#define N_ 64
#define C_ 64
#define T_ 300
#define V_ 25
#define S_ 3
#define IC_ 16
#define OC_ 64
#define EPS_ 1e-5f
#define TV_ (T_ * V_)

#define NCH 75
#define PP 100

#define P68 68     // 272B pitch (272/16=17 odd -> ldmatrix conflict-free)
#define P36 36     // 144B pitch (144/16=9 odd)

// ---- device-global scratch ----
__device__ float g_Mpart[N_ * NCH * S_ * 625];
__device__ float g_AadpT[N_ * S_ * 25 * P36];   // [n][s][w][v] tf32, v-pads zero
__device__ float g_wabM[96 * P68];              // [r=s*32+j][c] tf32
__device__ float g_wdPack[S_ * 4 * 8 * 128];    // [s][mt][k0][lane][4] A-fragments tf32
__device__ float g_bnc[192];                    // mul[96], add[96]
__device__ float g_obnc[128];                   // sc[64], sh[64]

__device__ __forceinline__ float tanh_fast(float x) {
    float cx = fminf(fmaxf(x, -10.0f), 10.0f);
    float e = __expf(2.0f * cx);
    return __fdividef(e - 1.0f, e + 1.0f);
}
__device__ __forceinline__ float to_tf32(float x) {
    uint32_t u;
    asm("cvt.rna.tf32.f32 %0, %1;" : "=r"(u) : "f"(x));
    return __uint_as_float(u);
}
__device__ __forceinline__ void mma_tf32(float c[4],
                                         uint32_t a0, uint32_t a1, uint32_t a2, uint32_t a3,
                                         uint32_t b0, uint32_t b1) {
    asm volatile("mma.sync.aligned.m16n8k8.row.col.f32.tf32.tf32.f32 "
                 "{%0,%1,%2,%3}, {%4,%5,%6,%7}, {%8,%9}, {%0,%1,%2,%3};"
                 : "+f"(c[0]), "+f"(c[1]), "+f"(c[2]), "+f"(c[3])
                 : "r"(a0), "r"(a1), "r"(a2), "r"(a3), "r"(b0), "r"(b1));
}
__device__ __forceinline__ void ldsm_x4(uint32_t& r0, uint32_t& r1, uint32_t& r2, uint32_t& r3,
                                        uint32_t a) {
    asm volatile("ldmatrix.sync.aligned.m8n8.x4.shared.b16 {%0,%1,%2,%3}, [%4];"
                 : "=r"(r0), "=r"(r1), "=r"(r2), "=r"(r3) : "r"(a));
}
__device__ __forceinline__ void ldsm_x2(uint32_t& r0, uint32_t& r1, uint32_t a) {
    asm volatile("ldmatrix.sync.aligned.m8n8.x2.shared.b16 {%0,%1}, [%2];"
                 : "=r"(r0), "=r"(r1) : "r"(a));
}
__device__ __forceinline__ uint32_t smem_u32(const void* p) {
    return (uint32_t)__cvta_generic_to_shared(p);
}

// =====================================================================
// k0: one-time prep of weight layouts + BN constants
// =====================================================================
__global__ void k0_prep(const float* __restrict__ wa, const float* __restrict__ ba,
                        const float* __restrict__ wb, const float* __restrict__ bb,
                        const float* __restrict__ gaA, const float* __restrict__ beA,
                        const float* __restrict__ mA,  const float* __restrict__ vA,
                        const float* __restrict__ gaB, const float* __restrict__ beB,
                        const float* __restrict__ mB,  const float* __restrict__ vB,
                        const float* __restrict__ wd,  const float* __restrict__ dbias,
                        const float* __restrict__ bng, const float* __restrict__ bnb,
                        const float* __restrict__ bnm, const float* __restrict__ bnv)
{
    int gid = blockIdx.x * blockDim.x + threadIdx.x;
    if (gid < 96 * P68) {
        int r = gid / P68, c = gid % P68;
        float val = 0.0f;
        if (c < C_) {
            int s = r >> 5, j = r & 31;
            val = to_tf32((j < IC_) ? wa[(s * IC_ + j) * C_ + c]
                                    : wb[(s * IC_ + (j - 16)) * C_ + c]);
        }
        g_wabM[gid] = val;
        return;
    }
    int g2 = gid - 96 * P68;
    if (g2 < S_ * 4 * 8 * 128) {
        // fragment-order pack: gid = (((s*4+mt)*8+k0)*32+lane)*4+reg
        int reg = g2 & 3;
        int lane = (g2 >> 2) & 31;
        int k0 = (g2 >> 7) & 7;
        int mt = (g2 >> 10) & 3;
        int s = g2 >> 12;
        int o = mt * 16 + (lane >> 2) + (reg & 1) * 8;
        int c = k0 * 8 + (lane & 3) + (reg >> 1) * 4;
        g_wdPack[g2] = to_tf32(wd[(s * OC_ + o) * C_ + c]);
        return;
    }
    int g3 = g2 - S_ * 4 * 8 * 128;
    if (g3 < 96) {
        int s = g3 >> 5, j = g3 & 31;
        int i = (j < IC_) ? j : j - 16;
        int off = s * IC_ + i;
        float g, be, mm, vv, bias;
        if (j < IC_) { g = gaA[off]; be = beA[off]; mm = mA[off]; vv = vA[off]; bias = ba[off]; }
        else         { g = gaB[off]; be = beB[off]; mm = mB[off]; vv = vB[off]; bias = bb[off]; }
        float sc = g * rsqrtf(vv + EPS_);
        g_bnc[g3] = sc;
        g_bnc[96 + g3] = be + (bias - mm) * sc;
        return;
    }
    int g4 = g3 - 96;
    if (g4 < OC_) {
        float scv = bng[g4] * rsqrtf(bnv[g4] + EPS_);
        g_obnc[g4] = scv;
        g_obnc[64 + g4] = bnb[g4] + (dbias[g4] + dbias[OC_ + g4] + dbias[2 * OC_ + g4] - bnm[g4]) * scv;
    }
}

// =====================================================================
// k1: per (n, 4-t chunk), mma.sync + ldmatrix, 3 CTAs/SM (unchanged)
// =====================================================================
__global__ __launch_bounds__(256, 3)
void k1_mpart(const float* __restrict__ x)
{
    extern __shared__ float sm1[];
    float* wabM = sm1;           // 96*68 = 6528   [r][c]
    float* xs2  = sm1 + 6528;    // 100*68 = 6800  [p][c]
    float* ab2  = sm1;           // stage2 overlay

    const int n = blockIdx.y, chunk = blockIdx.x, tid = threadIdx.x;
    const int lane = tid & 31, warp = tid >> 5;
    const int qk = lane & 3, qm = lane >> 2;

    for (int idx = tid; idx < 6528 / 4; idx += 256)
        ((float4*)wabM)[idx] = ((const float4*)g_wabM)[idx];
    const float* xbase = x + (size_t)n * (C_ * TV_) + chunk * PP;
    for (int t = tid; t < 400; t += 256) {
        int q = t % 25, c4 = t / 25;
        const float* src = xbase + (c4 * 4) * TV_ + q * 4;
        float4 r0 = *(const float4*)(src);
        float4 r1 = *(const float4*)(src + TV_);
        float4 r2 = *(const float4*)(src + 2 * TV_);
        float4 r3 = *(const float4*)(src + 3 * TV_);
        float4 o;
        o.x = r0.x; o.y = r1.x; o.z = r2.x; o.w = r3.x;
        *(float4*)(xs2 + (4 * q + 0) * P68 + c4 * 4) = o;
        o.x = r0.y; o.y = r1.y; o.z = r2.y; o.w = r3.y;
        *(float4*)(xs2 + (4 * q + 1) * P68 + c4 * 4) = o;
        o.x = r0.z; o.y = r1.z; o.z = r2.z; o.w = r3.z;
        *(float4*)(xs2 + (4 * q + 2) * P68 + c4 * 4) = o;
        o.x = r0.w; o.y = r1.w; o.z = r2.w; o.w = r3.w;
        *(float4*)(xs2 + (4 * q + 3) * P68 + c4 * 4) = o;
    }
    __syncthreads();

    float acc[13][4];
    if (warp < 6) {
        #pragma unroll
        for (int t = 0; t < 13; ++t)
            #pragma unroll
            for (int r = 0; r < 4; ++r) acc[t][r] = 0.0f;
        const uint32_t abase = smem_u32(wabM) + (warp * 16 + (lane & 15)) * 272
                             + ((lane >> 4) << 4);
        const uint32_t bbase = smem_u32(xs2) + (lane & 7) * 272 + (((lane >> 3) & 1) << 4);
        #pragma unroll
        for (int k0 = 0; k0 < 8; ++k0) {
            uint32_t a0, a1, a2, a3;
            ldsm_x4(a0, a1, a2, a3, abase + k0 * 32);
            #pragma unroll
            for (int nt = 0; nt < 13; ++nt) {
                uint32_t b0, b1;
                ldsm_x2(b0, b1, bbase + nt * 8 * 272 + k0 * 32);
                mma_tf32(acc[nt], a0, a1, a2, a3, b0, b1);
            }
        }
    }
    __syncthreads();

    if (warp < 6) {
        #pragma unroll
        for (int half = 0; half < 2; ++half) {
            int r = warp * 16 + qm + half * 8;
            float mu = g_bnc[r], ad = g_bnc[96 + r];
            int s = r >> 5, j = r & 31, i = j & 15;
            float* dstb = ab2 + s * 3400 + ((j < IC_) ? 0 : 1700);
            #pragma unroll
            for (int nt = 0; nt < 13; ++nt) {
                #pragma unroll
                for (int e = 0; e < 2; ++e) {
                    int p = nt * 8 + qk * 2 + e;
                    if (p < PP) {
                        int tl = p / 25, v = p - tl * 25;
                        float val = tanh_fast(fmaf(acc[nt][half * 2 + e], mu, ad));
                        dstb[v * P68 + i * 4 + tl] = val;
                    }
                }
            }
        }
    }
    __syncthreads();

    float* dst = g_Mpart + (size_t)(n * NCH + chunk) * (S_ * 625);
    #pragma unroll
    for (int ti = 0; ti < 3; ++ti) {
        int task = warp * 3 + ti;
        int s = task >> 3, mtv = (task >> 2) & 1, ntw = task & 3;
        const uint32_t abase = smem_u32(ab2 + s * 3400)
                             + (mtv * 16 + (lane & 15)) * 272 + ((lane >> 4) << 4);
        const uint32_t bbase = smem_u32(ab2 + s * 3400 + 1700)
                             + (ntw * 8 + (lane & 7)) * 272 + (((lane >> 3) & 1) << 4);
        float acc2[4] = {0.0f, 0.0f, 0.0f, 0.0f};
        #pragma unroll
        for (int k0 = 0; k0 < 8; ++k0) {
            uint32_t a0, a1, a2, a3, b0, b1;
            ldsm_x4(a0, a1, a2, a3, abase + k0 * 32);
            ldsm_x2(b0, b1, bbase + k0 * 32);
            mma_tf32(acc2, a0, a1, a2, a3, b0, b1);
        }
        #pragma unroll
        for (int half = 0; half < 2; ++half) {
            int v = mtv * 16 + qm + half * 8;
            #pragma unroll
            for (int e = 0; e < 2; ++e) {
                int w = ntw * 8 + qk * 2 + e;
                if (v < V_ && w < V_)
                    dst[s * 625 + v * 25 + w] = acc2[half * 2 + e];
            }
        }
    }
}

// =====================================================================
// k2: reduce partial M -> g_AadpT [n][s][w][v] tf32 (unchanged)
// =====================================================================
__global__ void k2_aadp(const float* __restrict__ A, const float* __restrict__ alpha)
{
    int gid = blockIdx.x * blockDim.x + threadIdx.x;
    if (gid >= N_ * S_ * 25 * P36) return;
    int n = gid / (S_ * 25 * P36);
    int rem = gid % (S_ * 25 * P36);
    int s = rem / (25 * P36);
    int r = rem % (25 * P36);
    int w = r / P36, v = r % P36;
    float val = 0.0f;
    if (v < V_) {
        const float* src = g_Mpart + (size_t)n * NCH * (S_ * 625) + s * 625 + v * 25 + w;
        float sum = 0.0f;
        #pragma unroll 5
        for (int ch = 0; ch < NCH; ++ch) sum += src[(size_t)ch * (S_ * 625)];
        val = to_tf32(A[s * 625 + v * 25 + w] + tanh_fast(sum * (1.0f / 4800.0f)) * alpha[0]);
    }
    g_AadpT[gid] = val;
}

// =====================================================================
// k3: phase1 U-GEMM (ldmatrix), phase2 Y-GEMM with packed A fragments
// (one LDG.128 per warp per k-step), fused epilogue. 3 CTAs/SM.
// =====================================================================
__global__ __launch_bounds__(256, 3)
void k3_main(const float* __restrict__ x, float* __restrict__ out)
{
    extern __shared__ float sm3[];
    float* as3T = sm3;           // 3*25*36 = 2700 [s][w][v]
    float* us2  = sm3 + 2700;    // 100*68 = 6800 [p][c]
    float* xsA  = sm3 + 9500;    // 256*36 = 9216 [(c,tl)][v]
    // total 18716 floats = 74864 B -> 3 CTAs/SM

    const int n = blockIdx.y, chunk = blockIdx.x, tid = threadIdx.x;
    const int lane = tid & 31, warp = tid >> 5;
    const int qk = lane & 3, qm = lane >> 2;

    const float* xbase = x + (size_t)n * (C_ * TV_) + chunk * PP;

    // ---- stage xsA [m=(c,tl)][v]
    for (int idx4 = tid; idx4 < 64 * 25; idx4 += 256) {
        int c = idx4 / 25, q = idx4 % 25;
        float4 r = *(const float4*)(xbase + c * TV_ + q * 4);
        #pragma unroll
        for (int j = 0; j < 4; ++j) {
            int p = 4 * q + j;
            int tl = p / 25, v = p - tl * 25;
            float val = (j == 0) ? r.x : (j == 1) ? r.y : (j == 2) ? r.z : r.w;
            xsA[(c * 4 + tl) * P36 + v] = val;
        }
    }
    for (int idx = tid; idx < 256 * 7; idx += 256) {
        int row = idx / 7, cc = 25 + idx % 7;
        xsA[row * P36 + cc] = 0.0f;
    }
    // ---- stage as3T: linear f4 copy
    {
        const float4* src = (const float4*)(g_AadpT + (size_t)n * (S_ * 25 * P36));
        for (int idx = tid; idx < (S_ * 25 * P36) / 4; idx += 256)
            ((float4*)as3T)[idx] = src[idx];
    }
    __syncthreads();

    const int mtY = warp >> 1;
    const int ntb = (warp & 1) ? 7 : 0;
    const int nnt = (warp & 1) ? 6 : 7;
    float accY[7][4];
    #pragma unroll
    for (int t = 0; t < 7; ++t)
        #pragma unroll
        for (int r = 0; r < 4; ++r) accY[t][r] = 0.0f;

    const uint32_t aoff = (lane & 15) * 144 + ((lane >> 4) << 4);
    const uint32_t boff36 = (lane & 7) * 144 + (((lane >> 3) & 1) << 4);
    const uint32_t boff68 = (lane & 7) * 272 + (((lane >> 3) & 1) << 4);

    for (int s = 0; s < S_; ++s) {
        // ---- phase1: warp owns m-tiles {warp, warp+8}; 4 nt; K=32
        {
            float acc1[2][4][4];
            #pragma unroll
            for (int m2 = 0; m2 < 2; ++m2)
                #pragma unroll
                for (int t = 0; t < 4; ++t)
                    #pragma unroll
                    for (int r = 0; r < 4; ++r) acc1[m2][t][r] = 0.0f;
            const uint32_t ab0 = smem_u32(xsA) + warp * 16 * 144 + aoff;
            const uint32_t ab1 = ab0 + 8 * 16 * 144;
            const uint32_t bb = smem_u32(as3T) + s * 900 * 4 + boff36;
            #pragma unroll
            for (int k0 = 0; k0 < 4; ++k0) {
                uint32_t a[2][4];
                ldsm_x4(a[0][0], a[0][1], a[0][2], a[0][3], ab0 + k0 * 32);
                ldsm_x4(a[1][0], a[1][1], a[1][2], a[1][3], ab1 + k0 * 32);
                #pragma unroll
                for (int nt = 0; nt < 4; ++nt) {
                    uint32_t b0, b1;
                    ldsm_x2(b0, b1, bb + nt * 8 * 144 + k0 * 32);
                    mma_tf32(acc1[0][nt], a[0][0], a[0][1], a[0][2], a[0][3], b0, b1);
                    mma_tf32(acc1[1][nt], a[1][0], a[1][1], a[1][2], a[1][3], b0, b1);
                }
            }
            // scatter U -> us2[p][c]
            #pragma unroll
            for (int m2 = 0; m2 < 2; ++m2) {
                #pragma unroll
                for (int half = 0; half < 2; ++half) {
                    int m = (warp + m2 * 8) * 16 + qm + half * 8;
                    int c = m >> 2, tl = m & 3;
                    #pragma unroll
                    for (int nt = 0; nt < 4; ++nt) {
                        #pragma unroll
                        for (int e = 0; e < 2; ++e) {
                            int w = nt * 8 + qk * 2 + e;
                            if (w < V_)
                                us2[(tl * 25 + w) * P68 + c] = acc1[m2][nt][half * 2 + e];
                        }
                    }
                }
            }
        }
        __syncthreads();

        // ---- phase2: A via ONE coalesced LDG.128 per k-step (packed frags),
        //      B via x2-ldmatrix from us2
        const float4* wp = (const float4*)g_wdPack + ((size_t)(s * 4 + mtY) * 8) * 32 + lane;
        const uint32_t ub = smem_u32(us2) + boff68;
        #pragma unroll
        for (int k0 = 0; k0 < 8; ++k0) {
            float4 av = wp[k0 * 32];
            uint32_t a0 = __float_as_uint(av.x);
            uint32_t a1 = __float_as_uint(av.y);
            uint32_t a2 = __float_as_uint(av.z);
            uint32_t a3 = __float_as_uint(av.w);
            #pragma unroll
            for (int j = 0; j < 7; ++j) {
                if (j < nnt) {
                    int nt = ntb + j;
                    uint32_t b0, b1;
                    ldsm_x2(b0, b1, ub + nt * 8 * 272 + k0 * 32);
                    mma_tf32(accY[j], a0, a1, a2, a3, b0, b1);
                }
            }
        }
        __syncthreads();   // us2 consumed; next s may overwrite
    }

    // ---- epilogue: BN + residual + relu
    float* obase = out + (size_t)n * (C_ * TV_) + chunk * PP;
    #pragma unroll
    for (int half = 0; half < 2; ++half) {
        int o = mtY * 16 + qm + half * 8;
        float sc = g_obnc[o], sh = g_obnc[64 + o];
        const float* xr = xbase + o * TV_;
        float* orow = obase + o * TV_;
        #pragma unroll
        for (int j = 0; j < 7; ++j) {
            if (j < nnt) {
                int nt = ntb + j;
                #pragma unroll
                for (int e = 0; e < 2; ++e) {
                    int p = nt * 8 + qk * 2 + e;
                    if (p < PP) {
                        float val = fmaf(accY[j][half * 2 + e], sc, sh) + xr[p];
                        orow[p] = fmaxf(val, 0.0f);
                    }
                }
            }
        }
    }
}

// =====================================================================
extern "C" void kernel_launch(void* const* d_in, const int* in_sizes, int n_in,
                              void* d_out, int out_size)
{
    const float* x    = (const float*)d_in[0];
    const float* A    = (const float*)d_in[1];
    const float* alph = (const float*)d_in[2];
    const float* wa   = (const float*)d_in[3];
    const float* ba   = (const float*)d_in[4];
    const float* wb   = (const float*)d_in[5];
    const float* bb   = (const float*)d_in[6];
    const float* bag  = (const float*)d_in[7];
    const float* bab  = (const float*)d_in[8];
    const float* bam  = (const float*)d_in[9];
    const float* bav  = (const float*)d_in[10];
    const float* bbg  = (const float*)d_in[11];
    const float* bbb  = (const float*)d_in[12];
    const float* bbm  = (const float*)d_in[13];
    const float* bbv  = (const float*)d_in[14];
    const float* wd   = (const float*)d_in[15];
    const float* db   = (const float*)d_in[16];
    const float* bng  = (const float*)d_in[17];
    const float* bnbt = (const float*)d_in[18];
    const float* bnm  = (const float*)d_in[19];
    const float* bnv  = (const float*)d_in[20];
    float* out = (float*)d_out;

    const int SM1 = 13616 * (int)sizeof(float); // 54464 B -> 3 CTAs
    const int SM3 = 18716 * (int)sizeof(float); // 74864 B -> 3 CTAs
    cudaFuncSetAttribute(k1_mpart, cudaFuncAttributeMaxDynamicSharedMemorySize, SM1);
    cudaFuncSetAttribute(k3_main,  cudaFuncAttributeMaxDynamicSharedMemorySize, SM3);

    int prep_elems = 96 * P68 + S_ * 4 * 8 * 128 + 96 + OC_;
    k0_prep<<<(prep_elems + 255) / 256, 256>>>(
        wa, ba, wb, bb, bag, bab, bam, bav, bbg, bbb, bbm, bbv,
        wd, db, bng, bnbt, bnm, bnv);

    dim3 g(NCH, N_);
    k1_mpart<<<g, 256, SM1>>>(x);

    k2_aadp<<<(N_ * S_ * 25 * P36 + 255) / 256, 256>>>(A, alph);

    k3_main<<<g, 256, SM3>>>(x, out);
}